// round 2
// baseline (speedup 1.0000x reference)
#include <cuda_runtime.h>
#include <math.h>

#define K 128
#define NN 10000
#define EE 160000
#define NE_ 10
#define NB_ 8
#define GG 16
#define NK (NN*K)

#define SQ3F 1.7320508075688772f
#define INV_SQ3 0.5773502691896258f
#define PI_F 3.14159265358979323846f
#define CB_F 0.6324555320336759f   /* sqrt(2/5) */
#define CDIV(a,b) (((a)+(b)-1)/(b))

/* ------------------- device scratch (no allocs allowed) ------------------ */
__device__ float g_sU1[NE_*K];     // W_embed[z] @ W_up1
__device__ float g_ssk1[NE_*K];    // per-z skip-1 table
__device__ float g_r[EE];
__device__ float g_Y1[EE*3];
__device__ float g_ef[EE*NB_];
__device__ int   g_esnd[EE], g_ercv[EE], g_ezsnd[EE];
__device__ int   g_nact;
__device__ float g_A0[NK];
__device__ float g_A1[3*NK];
__device__ float g_s1[NK];
__device__ float g_sU2[NK];
__device__ float g_vU2[3*NK];
__device__ float g_A2[NK];
__device__ float g_s2[NK];
__device__ float g_ds2[NK];
__device__ float g_dA2[NK];
__device__ float g_ds1[NK];
__device__ float g_Dsj2[NK];
__device__ float g_Dvj[3*NK];
__device__ float g_dA0[NK];
__device__ float g_dA1[3*NK];
__device__ float g_def[EE*NB_];
__device__ float g_dY1b[EE*3];
__device__ float g_e0[GG], g_e1[GG], g_e2[GG];
__device__ float g_WtA[K*K];       // W_mix_s1^T
__device__ float g_WtC[K*K];       // W_up2s^T
__device__ float g_WtE[K*K];       // W_mix_s2^T
__device__ float g_Wfuse[K*K];     // W_mix_v1 @ W_up2v
__device__ float g_WfuseT[K*K];
__device__ float g_Wsk2T[NE_*K*K];
__device__ int g_zcnt[NE_], g_zoff[NE_+1], g_zfill[NE_], g_zperm[NN];

/* ------------------------------- zero ------------------------------------ */
__global__ void zero_kernel(float* __restrict__ out, int out_size){
  int total = 3*NK;
  if (out_size > total) total = out_size;
  for (int i = blockIdx.x*blockDim.x + threadIdx.x; i < total; i += gridDim.x*blockDim.x){
    if (i < 3*NK){ g_A1[i]=0.f; g_Dvj[i]=0.f; }
    if (i < NK){ g_A0[i]=0.f; g_A2[i]=0.f; g_Dsj2[i]=0.f; }
    if (i < out_size) out[i]=0.f;
    if (i < GG){ g_e0[i]=0.f; g_e1[i]=0.f; g_e2[i]=0.f; }
    if (i < NE_){ g_zcnt[i]=0; g_zfill[i]=0; }
    if (i == 0) g_nact = 0;
  }
}

/* ------------------------- per-z tables ---------------------------------- */
__global__ void tab_kernel(const float* __restrict__ We, const float* __restrict__ Wu1,
                           const float* __restrict__ Wsk1){
  int z = blockIdx.x, d = threadIdx.x;
  float a = 0.f, b = 0.f;
  for (int c = 0; c < K; c++){
    float s = We[z*K + c];
    a = fmaf(s, Wu1[c*K + d], a);
    b = fmaf(s, Wsk1[(z*K + c)*K + d], b);
  }
  g_sU1[z*K + d] = a;
  g_ssk1[z*K + d] = b;
}

/* ------------------------------ transpose -------------------------------- */
__global__ void transpose_kernel(const float* __restrict__ src, float* __restrict__ dst, int nmat){
  int total = nmat*K*K;
  for (int i = blockIdx.x*blockDim.x + threadIdx.x; i < total; i += gridDim.x*blockDim.x){
    int m = i/(K*K); int rem = i - m*K*K; int r = rem/K; int c = rem - r*K;
    dst[m*K*K + c*K + r] = src[i];
  }
}

/* ------------------------- node grouping by z ---------------------------- */
__global__ void zcount_kernel(const int* __restrict__ nz){
  int n = blockIdx.x*blockDim.x + threadIdx.x;
  if (n < NN) atomicAdd(&g_zcnt[nz[n]], 1);
}
__global__ void zscan_kernel(){
  if (threadIdx.x == 0 && blockIdx.x == 0){
    int acc = 0;
    for (int z = 0; z < NE_; z++){ g_zoff[z] = acc; acc += g_zcnt[z]; }
    g_zoff[NE_] = acc;
  }
}
__global__ void zscatter_kernel(const int* __restrict__ nz){
  int n = blockIdx.x*blockDim.x + threadIdx.x;
  if (n < NN){
    int z = nz[n];
    int p = atomicAdd(&g_zfill[z], 1);
    g_zperm[g_zoff[z] + p] = n;
  }
}

/* ------------------------- geometry + edge compaction -------------------- */
__global__ void geom_kernel(const float* __restrict__ pos, const float* __restrict__ shifts,
                            const int* __restrict__ ei, const int* __restrict__ nz){
  int e = blockIdx.x*blockDim.x + threadIdx.x;
  if (e >= EE) return;
  int s = ei[e], rc = ei[EE + e];
  float vx = pos[rc*3+0] - pos[s*3+0] + shifts[e*3+0];
  float vy = pos[rc*3+1] - pos[s*3+1] + shifts[e*3+1];
  float vz = pos[rc*3+2] - pos[s*3+2] + shifts[e*3+2];
  float rr = sqrtf(vx*vx + vy*vy + vz*vz + 1e-12f);
  if (rr < 5.0f){
    int i = atomicAdd(&g_nact, 1);
    g_esnd[i]=s; g_ercv[i]=rc; g_ezsnd[i]=nz[s];
    g_r[i]=rr;
    float inv = SQ3F / rr;
    g_Y1[i*3+0]=vx*inv; g_Y1[i*3+1]=vy*inv; g_Y1[i*3+2]=vz*inv;
    float x = rr*0.2f;
    float x2=x*x, x4=x2*x2, x5=x4*x;
    float fc = 1.f + x5*(-21.f + x*(35.f - 15.f*x));
    float invr = 1.f/rr;
    #pragma unroll
    for (int b = 0; b < NB_; b++){
      float a = (float)(b+1)*(PI_F*0.2f);
      g_ef[i*NB_ + b] = CB_F * sinf(a*rr) * invr * fc;
    }
  }
}

__global__ void e0_kernel(const int* __restrict__ nz, const int* __restrict__ batch,
                          const float* __restrict__ ae){
  int n = blockIdx.x*blockDim.x + threadIdx.x;
  if (n < NN) atomicAdd(&g_e0[batch[n]], ae[nz[n]]);
}

/* --------------------------- layer-1 messages ---------------------------- */
__global__ void __launch_bounds__(128) msg1_kernel(const float* __restrict__ R1){
  int c = threadIdx.x;
  float r1a[NB_], r1b[NB_];
  #pragma unroll
  for (int b = 0; b < NB_; b++){ r1a[b]=R1[b*256 + c]; r1b[b]=R1[b*256 + 128 + c]; }
  int nact = g_nact;
  for (int e = blockIdx.x; e < nact; e += gridDim.x){
    int rcv = g_ercv[e], zs = g_ezsnd[e];
    float y0=g_Y1[e*3+0], y1=g_Y1[e*3+1], y2=g_Y1[e*3+2];
    float w0=0.f, w1=0.f;
    #pragma unroll
    for (int b = 0; b < NB_; b++){ float efb=g_ef[e*NB_+b]; w0=fmaf(efb,r1a[b],w0); w1=fmaf(efb,r1b[b],w1); }
    float sj = g_sU1[zs*K + c];
    atomicAdd(&g_A0[rcv*K + c], w0*sj);
    float t = w1*sj;
    atomicAdd(&g_A1[rcv*K + c],        t*y0);
    atomicAdd(&g_A1[NK + rcv*K + c],   t*y1);
    atomicAdd(&g_A1[2*NK + rcv*K + c], t*y2);
  }
}

/* ------------------------------ node GEMM -------------------------------- */
/* C[n,:] = alpha * A[n,:]@B (+C if accum) (+table[nz[n],:]) (+bias[:])      */
__global__ void __launch_bounds__(128) gemm_kernel(const float* __restrict__ A,
    const float* __restrict__ B, float* __restrict__ C, int M, float alpha, int accum,
    const float* __restrict__ table, const int* __restrict__ nz,
    const float* __restrict__ bias){
  __shared__ float As[32][K];
  int d = threadIdx.x;
  int m0 = blockIdx.x*32;
  int rows = M - m0; if (rows > 32) rows = 32;
  for (int i = 0; i < 32; i++) As[i][d] = (i < rows) ? A[(m0+i)*K + d] : 0.f;
  __syncthreads();
  float acc[32];
  #pragma unroll
  for (int i = 0; i < 32; i++) acc[i] = 0.f;
  for (int c = 0; c < K; c += 4){
    float bv0=B[c*K+d], bv1=B[(c+1)*K+d], bv2=B[(c+2)*K+d], bv3=B[(c+3)*K+d];
    #pragma unroll
    for (int i = 0; i < 32; i++){
      float4 av = *(const float4*)&As[i][c];
      acc[i] = fmaf(av.x,bv0,fmaf(av.y,bv1,fmaf(av.z,bv2,fmaf(av.w,bv3,acc[i]))));
    }
  }
  for (int i = 0; i < rows; i++){
    int n = m0 + i;
    float v = alpha*acc[i];
    if (accum) v += C[n*K + d];
    if (table) v += table[nz[n]*K + d];
    if (bias)  v += bias[d];
    C[n*K + d] = v;
  }
}

/* z-grouped GEMM: rows via g_zperm, B matrix selected by z = blockIdx.y */
__global__ void __launch_bounds__(128) gemm_grouped_kernel(const float* __restrict__ A,
    const float* __restrict__ Bz, float* __restrict__ C, int accum){
  __shared__ float As[32][K];
  __shared__ int rowsIdx[32];
  int z = blockIdx.y;
  int start = g_zoff[z], cnt = g_zoff[z+1] - start;
  int m0 = blockIdx.x*32;
  if (m0 >= cnt) return;
  int rows = cnt - m0; if (rows > 32) rows = 32;
  int d = threadIdx.x;
  if (d < 32) rowsIdx[d] = (d < rows) ? g_zperm[start + m0 + d] : 0;
  __syncthreads();
  for (int i = 0; i < 32; i++) As[i][d] = (i < rows) ? A[rowsIdx[i]*K + d] : 0.f;
  __syncthreads();
  const float* B = Bz + z*K*K;
  float acc[32];
  #pragma unroll
  for (int i = 0; i < 32; i++) acc[i] = 0.f;
  for (int c = 0; c < K; c += 4){
    float bv0=B[c*K+d], bv1=B[(c+1)*K+d], bv2=B[(c+2)*K+d], bv3=B[(c+3)*K+d];
    #pragma unroll
    for (int i = 0; i < 32; i++){
      float4 av = *(const float4*)&As[i][c];
      acc[i] = fmaf(av.x,bv0,fmaf(av.y,bv1,fmaf(av.z,bv2,fmaf(av.w,bv3,acc[i]))));
    }
  }
  for (int i = 0; i < rows; i++){
    int n = rowsIdx[i];
    float v = acc[i];
    if (accum) v += C[n*K + d];
    C[n*K + d] = v;
  }
}

/* ------------------------------ e1 --------------------------------------- */
__global__ void e1_kernel(const float* __restrict__ wr1, const int* __restrict__ batch){
  int n = blockIdx.x*blockDim.x + threadIdx.x;
  if (n >= NN) return;
  float acc = 0.f;
  #pragma unroll 16
  for (int c = 0; c < K; c++) acc = fmaf(g_s1[n*K+c], wr1[c], acc);
  atomicAdd(&g_e1[batch[n]], acc);
}

/* --------------------------- layer-2 messages ---------------------------- */
__global__ void __launch_bounds__(128) msg2_kernel(const float* __restrict__ R2){
  int c = threadIdx.x;
  float r2a[NB_], r2b[NB_];
  #pragma unroll
  for (int b = 0; b < NB_; b++){ r2a[b]=R2[b*512 + c]; r2b[b]=R2[b*512 + 128 + c]; }
  int nact = g_nact;
  for (int e = blockIdx.x; e < nact; e += gridDim.x){
    int snd = g_esnd[e], rcv = g_ercv[e];
    float y0=g_Y1[e*3+0], y1=g_Y1[e*3+1], y2=g_Y1[e*3+2];
    float w00=0.f, w110=0.f;
    #pragma unroll
    for (int b = 0; b < NB_; b++){ float efb=g_ef[e*NB_+b]; w00=fmaf(efb,r2a[b],w00); w110=fmaf(efb,r2b[b],w110); }
    float sj = g_sU2[snd*K + c];
    float vj0=g_vU2[snd*K+c], vj1=g_vU2[NK+snd*K+c], vj2=g_vU2[2*NK+snd*K+c];
    float dot = vj0*y0 + vj1*y1 + vj2*y2;
    float m = fmaf(w00, sj, w110*dot*INV_SQ3);
    atomicAdd(&g_A2[rcv*K + c], m);
  }
}

/* ----------------------- MLP head: e2 + ds2 ------------------------------ */
__global__ void __launch_bounds__(128) mlp_kernel(const float* __restrict__ Wmlp,
    const float* __restrict__ wout, const int* __restrict__ batch){
  __shared__ float srow[K];
  __shared__ float gj[16];
  __shared__ float hpart[16];
  int tid = threadIdx.x;
  for (int n = blockIdx.x; n < NN; n += gridDim.x){
    srow[tid] = g_s2[n*K + tid];
    __syncthreads();
    if (tid < 16){
      float u = 0.f;
      for (int c = 0; c < K; c++) u = fmaf(srow[c], Wmlp[c*16 + tid], u);
      float sig = 1.f/(1.f + __expf(-u));
      hpart[tid] = u*sig*wout[tid];
      gj[tid] = wout[tid]*sig*(1.f + u*(1.f - sig));
    }
    __syncthreads();
    if (tid == 0){
      float s = 0.f;
      #pragma unroll
      for (int j = 0; j < 16; j++) s += hpart[j];
      atomicAdd(&g_e2[batch[n]], s);
    }
    float ds = 0.f;
    #pragma unroll
    for (int j = 0; j < 16; j++) ds = fmaf(Wmlp[tid*16 + j], gj[j], ds);
    g_ds2[n*K + tid] = ds;
    __syncthreads();
  }
}

/* ------------------------- backward: layer-2 edges ----------------------- */
__device__ __forceinline__ float warpsum(float v){
  #pragma unroll
  for (int o = 16; o; o >>= 1) v += __shfl_down_sync(0xffffffffu, v, o);
  return v;
}

__global__ void __launch_bounds__(128) bwd2_kernel(const float* __restrict__ R2){
  __shared__ float red[4][11];
  int c = threadIdx.x;
  int warp = c >> 5, lane = c & 31;
  float r2a[NB_], r2b[NB_];
  #pragma unroll
  for (int b = 0; b < NB_; b++){ r2a[b]=R2[b*512 + c]; r2b[b]=R2[b*512 + 128 + c]; }
  int nact = g_nact;
  for (int e = blockIdx.x; e < nact; e += gridDim.x){
    int snd = g_esnd[e], rcv = g_ercv[e];
    float y0=g_Y1[e*3+0], y1=g_Y1[e*3+1], y2=g_Y1[e*3+2];
    float w00=0.f, w110=0.f;
    #pragma unroll
    for (int b = 0; b < NB_; b++){ float efb=g_ef[e*NB_+b]; w00=fmaf(efb,r2a[b],w00); w110=fmaf(efb,r2b[b],w110); }
    float dm = g_dA2[rcv*K + c];                 /* already includes /AVG  */
    float sj = g_sU2[snd*K + c];
    float vj0=g_vU2[snd*K+c], vj1=g_vU2[NK+snd*K+c], vj2=g_vU2[2*NK+snd*K+c];
    float dot = vj0*y0 + vj1*y1 + vj2*y2;
    float dsj = dm*w00;
    atomicAdd(&g_Dsj2[snd*K + c], dsj);
    float ddot = dm*w110*INV_SQ3;
    atomicAdd(&g_Dvj[snd*K + c],        ddot*y0);
    atomicAdd(&g_Dvj[NK + snd*K + c],   ddot*y1);
    atomicAdd(&g_Dvj[2*NK + snd*K + c], ddot*y2);
    float p[11];
    float dw00 = dm*sj, dw110 = dm*dot*INV_SQ3;
    #pragma unroll
    for (int b = 0; b < NB_; b++) p[b] = fmaf(dw00, r2a[b], dw110*r2b[b]);
    p[8] = ddot*vj0; p[9] = ddot*vj1; p[10] = ddot*vj2;
    #pragma unroll
    for (int k = 0; k < 11; k++){
      float v = warpsum(p[k]);
      if (lane == 0) red[warp][k] = v;
    }
    __syncthreads();
    if (c < 11){
      float v = red[0][c] + red[1][c] + red[2][c] + red[3][c];
      if (c < 8) g_def[e*NB_ + c] = v;
      else       g_dY1b[e*3 + (c-8)] = v;
    }
    __syncthreads();
  }
}

/* ------------------------- backward: layer-1 edges ----------------------- */
__global__ void __launch_bounds__(128) bwd1_kernel(const float* __restrict__ R1){
  __shared__ float red[4][11];
  int c = threadIdx.x;
  int warp = c >> 5, lane = c & 31;
  float r1a[NB_], r1b[NB_];
  #pragma unroll
  for (int b = 0; b < NB_; b++){ r1a[b]=R1[b*256 + c]; r1b[b]=R1[b*256 + 128 + c]; }
  int nact = g_nact;
  for (int e = blockIdx.x; e < nact; e += gridDim.x){
    int rcv = g_ercv[e], zs = g_ezsnd[e];
    float y0=g_Y1[e*3+0], y1=g_Y1[e*3+1], y2=g_Y1[e*3+2];
    float w1 = 0.f;
    #pragma unroll
    for (int b = 0; b < NB_; b++){ float efb=g_ef[e*NB_+b]; w1 = fmaf(efb, r1b[b], w1); }
    float dm0 = g_dA0[rcv*K + c];                /* includes /AVG */
    float dm10 = g_dA1[rcv*K + c];
    float dm11 = g_dA1[NK + rcv*K + c];
    float dm12 = g_dA1[2*NK + rcv*K + c];
    float sj = g_sU1[zs*K + c];
    float dw0 = dm0*sj;
    float t = dm10*y0 + dm11*y1 + dm12*y2;
    float dw1 = t*sj;
    float p[11];
    #pragma unroll
    for (int b = 0; b < NB_; b++) p[b] = fmaf(dw0, r1a[b], dw1*r1b[b]);
    float ws = w1*sj;
    p[8] = dm10*ws; p[9] = dm11*ws; p[10] = dm12*ws;
    #pragma unroll
    for (int k = 0; k < 11; k++){
      float v = warpsum(p[k]);
      if (lane == 0) red[warp][k] = v;
    }
    __syncthreads();
    if (c < 11){
      float v = red[0][c] + red[1][c] + red[2][c] + red[3][c];
      if (c < 8) g_def[e*NB_ + c] += v;
      else       g_dY1b[e*3 + (c-8)] += v;
    }
    __syncthreads();
  }
}

/* ------------------------- geometry backward ----------------------------- */
__global__ void geom_bwd_kernel(float* __restrict__ F){
  int nact = g_nact;
  for (int e = blockIdx.x*blockDim.x + threadIdx.x; e < nact; e += gridDim.x*blockDim.x){
    float rr = g_r[e];
    float y0=g_Y1[e*3+0], y1=g_Y1[e*3+1], y2=g_Y1[e*3+2];
    float v0 = y0*rr*INV_SQ3, v1 = y1*rr*INV_SQ3, v2 = y2*rr*INV_SQ3;
    float x = rr*0.2f;
    float x2=x*x, x4=x2*x2, x5=x4*x;
    float fc = 1.f + x5*(-21.f + x*(35.f - 15.f*x));
    float omx = 1.f - x;
    float dfcdr = -21.f*x4*omx*omx;
    float invr = 1.f/rr;
    float dr = 0.f;
    #pragma unroll
    for (int b = 0; b < NB_; b++){
      float a = (float)(b+1)*(PI_F*0.2f);
      float sn, co; sincosf(a*rr, &sn, &co);
      float debdr = CB_F*((a*co*rr - sn)*invr*invr*fc + sn*invr*dfcdr);
      dr = fmaf(g_def[e*NB_ + b], debdr, dr);
    }
    float dY0=g_dY1b[e*3+0], dY1v=g_dY1b[e*3+1], dY2=g_dY1b[e*3+2];
    float vd = v0*dY0 + v1*dY1v + v2*dY2;
    float c1 = SQ3F*invr;
    float c2 = SQ3F*vd*invr*invr*invr;
    float dv0 = dr*v0*invr + c1*dY0 - c2*v0;
    float dv1 = dr*v1*invr + c1*dY1v - c2*v1;
    float dv2 = dr*v2*invr + c1*dY2 - c2*v2;
    int snd = g_esnd[e], rcv = g_ercv[e];
    atomicAdd(&F[snd*3+0],  dv0); atomicAdd(&F[snd*3+1],  dv1); atomicAdd(&F[snd*3+2],  dv2);
    atomicAdd(&F[rcv*3+0], -dv0); atomicAdd(&F[rcv*3+1], -dv1); atomicAdd(&F[rcv*3+2], -dv2);
  }
}

/* ------------------------------- finalize -------------------------------- */
__global__ void finalize_kernel(float* __restrict__ out){
  int g = threadIdx.x;
  if (g < GG){
    float a = g_e0[g], b = g_e1[g], c = g_e2[g];
    out[g] = a + b + c;
    out[GG + g*3 + 0] = a;
    out[GG + g*3 + 1] = b;
    out[GG + g*3 + 2] = c;
  }
}

/* ------------------------------ launch ----------------------------------- */
extern "C" void kernel_launch(void* const* d_in, const int* in_sizes, int n_in,
                              void* d_out, int out_size){
  const float *positions, *shifts, *ae, *We, *R1, *Wu1, *Wms1, *Wmv1, *Wsk1, *wr1;
  const float *R2, *Wu2s, *Wu2v, *Wms2, *Wsk2, *Wmlp, *wout;
  const int *edge_index, *node_z, *batch;

  if (in_sizes[2] == 2*EE){  /* setup_inputs dict order */
    positions=(const float*)d_in[0]; shifts=(const float*)d_in[1];
    edge_index=(const int*)d_in[2]; node_z=(const int*)d_in[3]; batch=(const int*)d_in[4];
    ae=(const float*)d_in[5]; We=(const float*)d_in[6]; R1=(const float*)d_in[7];
    Wu1=(const float*)d_in[8]; Wms1=(const float*)d_in[9]; Wmv1=(const float*)d_in[10];
    Wsk1=(const float*)d_in[11]; wr1=(const float*)d_in[12]; R2=(const float*)d_in[13];
    Wu2s=(const float*)d_in[14]; Wu2v=(const float*)d_in[15]; Wms2=(const float*)d_in[16];
    Wsk2=(const float*)d_in[17]; Wmlp=(const float*)d_in[18]; wout=(const float*)d_in[19];
  } else {                   /* reference signature order */
    positions=(const float*)d_in[0]; shifts=(const float*)d_in[1];
    ae=(const float*)d_in[2]; We=(const float*)d_in[3]; R1=(const float*)d_in[4];
    Wu1=(const float*)d_in[5]; Wms1=(const float*)d_in[6]; Wmv1=(const float*)d_in[7];
    Wsk1=(const float*)d_in[8]; wr1=(const float*)d_in[9]; R2=(const float*)d_in[10];
    Wu2s=(const float*)d_in[11]; Wu2v=(const float*)d_in[12]; Wms2=(const float*)d_in[13];
    Wsk2=(const float*)d_in[14]; Wmlp=(const float*)d_in[15]; wout=(const float*)d_in[16];
    edge_index=(const int*)d_in[17]; node_z=(const int*)d_in[18]; batch=(const int*)d_in[19];
  }
  float* out = (float*)d_out;

  float *p_sU1,*p_ssk1,*p_A0,*p_A1,*p_s1,*p_sU2,*p_vU2,*p_A2,*p_s2,*p_ds2,*p_dA2;
  float *p_ds1,*p_Dsj2,*p_Dvj,*p_dA0,*p_dA1,*p_WtA,*p_WtC,*p_WtE,*p_Wfuse,*p_WfuseT,*p_Wsk2T;
  cudaGetSymbolAddress((void**)&p_sU1, g_sU1);   cudaGetSymbolAddress((void**)&p_ssk1, g_ssk1);
  cudaGetSymbolAddress((void**)&p_A0, g_A0);     cudaGetSymbolAddress((void**)&p_A1, g_A1);
  cudaGetSymbolAddress((void**)&p_s1, g_s1);     cudaGetSymbolAddress((void**)&p_sU2, g_sU2);
  cudaGetSymbolAddress((void**)&p_vU2, g_vU2);   cudaGetSymbolAddress((void**)&p_A2, g_A2);
  cudaGetSymbolAddress((void**)&p_s2, g_s2);     cudaGetSymbolAddress((void**)&p_ds2, g_ds2);
  cudaGetSymbolAddress((void**)&p_dA2, g_dA2);   cudaGetSymbolAddress((void**)&p_ds1, g_ds1);
  cudaGetSymbolAddress((void**)&p_Dsj2, g_Dsj2); cudaGetSymbolAddress((void**)&p_Dvj, g_Dvj);
  cudaGetSymbolAddress((void**)&p_dA0, g_dA0);   cudaGetSymbolAddress((void**)&p_dA1, g_dA1);
  cudaGetSymbolAddress((void**)&p_WtA, g_WtA);   cudaGetSymbolAddress((void**)&p_WtC, g_WtC);
  cudaGetSymbolAddress((void**)&p_WtE, g_WtE);   cudaGetSymbolAddress((void**)&p_Wfuse, g_Wfuse);
  cudaGetSymbolAddress((void**)&p_WfuseT, g_WfuseT); cudaGetSymbolAddress((void**)&p_Wsk2T, g_Wsk2T);

  const float ALPHA = 1.0f/16.0f;

  zero_kernel<<<4096, 512>>>(out, out_size);
  tab_kernel<<<NE_, K>>>(We, Wu1, Wsk1);
  transpose_kernel<<<32, 512>>>(Wms1, p_WtA, 1);
  transpose_kernel<<<32, 512>>>(Wu2s, p_WtC, 1);
  transpose_kernel<<<32, 512>>>(Wms2, p_WtE, 1);
  transpose_kernel<<<320, 512>>>(Wsk2, p_Wsk2T, NE_);
  gemm_kernel<<<CDIV(K,32), 128>>>(Wmv1, Wu2v, p_Wfuse, K, 1.0f, 0, 0, 0, 0);
  transpose_kernel<<<32, 512>>>(p_Wfuse, p_WfuseT, 1);
  zcount_kernel<<<CDIV(NN,256), 256>>>(node_z);
  zscan_kernel<<<1, 1>>>();
  zscatter_kernel<<<CDIV(NN,256), 256>>>(node_z);
  geom_kernel<<<CDIV(EE,256), 256>>>(positions, shifts, edge_index, node_z);
  e0_kernel<<<CDIV(NN,256), 256>>>(node_z, batch, ae);

  /* ------ layer 1 forward ------ */
  msg1_kernel<<<2048, 128>>>(R1);
  gemm_kernel<<<CDIV(NN,32), 128>>>(p_A0, Wms1, p_s1, NN, ALPHA, 0, p_ssk1, node_z, 0);
  e1_kernel<<<CDIV(NN,128), 128>>>(wr1, batch);

  /* ------ layer 2 forward ------ */
  gemm_kernel<<<CDIV(NN,32), 128>>>(p_s1, Wu2s, p_sU2, NN, 1.0f, 0, 0, 0, 0);
  gemm_kernel<<<CDIV(3*NN,32), 128>>>(p_A1, p_Wfuse, p_vU2, 3*NN, ALPHA, 0, 0, 0, 0);
  msg2_kernel<<<2048, 128>>>(R2);
  gemm_kernel<<<CDIV(NN,32), 128>>>(p_A2, Wms2, p_s2, NN, ALPHA, 0, 0, 0, 0);
  {
    dim3 grid(CDIV(NN,32), NE_);
    gemm_grouped_kernel<<<grid, 128>>>(p_s1, Wsk2, p_s2, 1);
  }
  mlp_kernel<<<2048, 128>>>(Wmlp, wout, batch);

  /* ------ backward ------ */
  gemm_kernel<<<CDIV(NN,32), 128>>>(p_ds2, p_WtE, p_dA2, NN, ALPHA, 0, 0, 0, 0);
  bwd2_kernel<<<2048, 128>>>(R2);
  {
    dim3 grid(CDIV(NN,32), NE_);
    gemm_grouped_kernel<<<grid, 128>>>(p_ds2, p_Wsk2T, p_ds1, 0);
  }
  gemm_kernel<<<CDIV(NN,32), 128>>>(p_Dsj2, p_WtC, p_ds1, NN, 1.0f, 1, 0, 0, wr1);
  gemm_kernel<<<CDIV(NN,32), 128>>>(p_ds1, p_WtA, p_dA0, NN, ALPHA, 0, 0, 0, 0);
  gemm_kernel<<<CDIV(3*NN,32), 128>>>(p_Dvj, p_WfuseT, p_dA1, 3*NN, ALPHA, 0, 0, 0, 0);
  bwd1_kernel<<<2048, 128>>>(R1);
  geom_bwd_kernel<<<1024, 256>>>(out + GG + 3*GG);
  finalize_kernel<<<1, 32>>>(out);
}

// round 3
// speedup vs baseline: 1.0971x; 1.0971x over previous
#include <cuda_runtime.h>
#include <math.h>

#define K 128
#define KK (K*K)
#define NN 10000
#define EE 160000
#define NE_ 10
#define NB_ 8
#define GG 16
#define NK (NN*K)

#define SQ3F 1.7320508075688772f
#define INV_SQ3 0.5773502691896258f
#define PI_F 3.14159265358979323846f
#define CB_F 0.6324555320336759f   /* sqrt(2/5) */
#define ALPHA_ (1.0f/16.0f)
#define CDIV(a,b) (((a)+(b)-1)/(b))

/* ------------------- device scratch (no allocs allowed) ------------------ */
__device__ float g_sU1[NE_*K];      // W_embed[z] @ W_up1
__device__ float g_tabU2[NE_*K];    // ssk1[z] @ W_up2s
__device__ float g_tabS2[NE_*K];    // ssk1[z] @ W_sk_s2[z]
__device__ float g_t1[NE_];         // ssk1[z] . wr1
__device__ float g_u[K];            // W_mix_s1 @ wr1
__device__ float g_r[EE];
__device__ float g_Y1[EE*3];
__device__ float g_ef[EE*NB_];
__device__ int   g_esnd[EE], g_ercv[EE], g_ezsnd[EE];
__device__ int   g_nact;
__device__ float g_A0[NK];
__device__ float g_A1[3*NK];
__device__ float g_sU2[NK];
__device__ float g_vU2[3*NK];
__device__ float g_A2[NK];
__device__ float g_s2[NK];
__device__ float g_ds2[NK];
__device__ float g_dA2[NK];
__device__ float g_Dsj2[NK];
__device__ float g_Dvj[3*NK];
__device__ float g_dA0[NK];
__device__ float g_dA1[3*NK];
__device__ float g_def[EE*NB_];
__device__ float g_dY1b[EE*3];
__device__ float g_e0[GG], g_e1[GG], g_e2[GG];
/* fused weights: [0]=WF1=Wms1@Wu2s, [1]=Wfuse=Wmv1@Wu2v, [2+z]=WF2z=Wms1@Wsk2[z] */
__device__ float g_WF[12*KK];
__device__ float g_WFT[12*KK];
__device__ float g_WtE[KK];         // Wms2^T
__device__ int g_zcnt[NE_], g_zoff[NE_+1], g_zfill[NE_], g_zperm[NN];

/* ------------------------------- zero ------------------------------------ */
__global__ void zero_kernel(float* __restrict__ out, int out_size){
  int total = 3*NK;
  if (out_size > total) total = out_size;
  for (int i = blockIdx.x*blockDim.x + threadIdx.x; i < total; i += gridDim.x*blockDim.x){
    if (i < 3*NK){ g_A1[i]=0.f; g_Dvj[i]=0.f; }
    if (i < NK){ g_A0[i]=0.f; g_A2[i]=0.f; g_Dsj2[i]=0.f; }
    if (i < out_size) out[i]=0.f;
    if (i < GG){ g_e0[i]=0.f; g_e1[i]=0.f; g_e2[i]=0.f; }
    if (i < NE_){ g_zcnt[i]=0; g_zfill[i]=0; }
    if (i == 0) g_nact = 0;
  }
}

/* ---------------------- multi-op node GEMM ------------------------------- */
/* C[n,:] = alpha*A[n,:]@B (+C if accum) (+table[nz[n],:]) (+alpha*bias[:])  */
#define MAXOPS 12
struct GOps {
  int count;
  int tiles[MAXOPS];
  const float* A[MAXOPS];
  const float* B[MAXOPS];
  float* C[MAXOPS];
  const float* table[MAXOPS];
  const float* bias[MAXOPS];
  const int* nz[MAXOPS];
  int M[MAXOPS];
  int accum[MAXOPS];
  float alpha[MAXOPS];
};

__global__ void __launch_bounds__(256) mgemm_kernel(GOps P){
  __shared__ float As[64][K];
  int b = blockIdx.x, op = 0;
  while (b >= P.tiles[op]){ b -= P.tiles[op]; op++; }
  int d = threadIdx.x & 127;
  int g = threadIdx.x >> 7;        /* 0/1: which 32-row half */
  int M = P.M[op];
  const float* __restrict__ A = P.A[op];
  int base0 = b*64;
  #pragma unroll 4
  for (int i = 0; i < 32; i++){
    int r = g*32 + i;
    As[r][d] = (base0 + r < M) ? A[(base0 + r)*K + d] : 0.f;
  }
  __syncthreads();
  const float* __restrict__ B = P.B[op];
  float acc[32];
  #pragma unroll
  for (int i = 0; i < 32; i++) acc[i] = 0.f;
  for (int c = 0; c < K; c += 4){
    float b0=B[c*K+d], b1=B[(c+1)*K+d], b2=B[(c+2)*K+d], b3=B[(c+3)*K+d];
    #pragma unroll
    for (int i = 0; i < 32; i++){
      float4 av = *(const float4*)&As[g*32 + i][c];
      acc[i] = fmaf(av.x,b0,fmaf(av.y,b1,fmaf(av.z,b2,fmaf(av.w,b3,acc[i]))));
    }
  }
  float alpha = P.alpha[op];
  float* __restrict__ C = P.C[op];
  const float* tab = P.table[op];
  const float* bias = P.bias[op];
  const int* nz = P.nz[op];
  int accum = P.accum[op];
  int base = base0 + g*32;
  for (int i = 0; i < 32; i++){
    int n = base + i;
    if (n >= M) break;
    float v = alpha*acc[i];
    if (accum) v += C[n*K + d];
    if (tab)   v += tab[nz[n]*K + d];
    if (bias)  v += alpha*bias[d];
    C[n*K + d] = v;
  }
}

/* z-grouped GEMM: rows via g_zperm, B matrix selected by z = blockIdx.y     */
__global__ void __launch_bounds__(128) gemm_grouped_kernel(const float* __restrict__ A,
    const float* __restrict__ Bz, float* __restrict__ C, float alpha, int accum,
    const float* __restrict__ tableZ){
  __shared__ float As[32][K];
  __shared__ int rowsIdx[32];
  int z = blockIdx.y;
  int start = g_zoff[z], cnt = g_zoff[z+1] - start;
  int m0 = blockIdx.x*32;
  if (m0 >= cnt) return;
  int rows = cnt - m0; if (rows > 32) rows = 32;
  int d = threadIdx.x;
  if (d < 32) rowsIdx[d] = (d < rows) ? g_zperm[start + m0 + d] : 0;
  __syncthreads();
  for (int i = 0; i < 32; i++) As[i][d] = (i < rows) ? A[rowsIdx[i]*K + d] : 0.f;
  __syncthreads();
  const float* B = Bz + z*KK;
  float acc[32];
  #pragma unroll
  for (int i = 0; i < 32; i++) acc[i] = 0.f;
  for (int c = 0; c < K; c += 4){
    float b0=B[c*K+d], b1=B[(c+1)*K+d], b2=B[(c+2)*K+d], b3=B[(c+3)*K+d];
    #pragma unroll
    for (int i = 0; i < 32; i++){
      float4 av = *(const float4*)&As[i][c];
      acc[i] = fmaf(av.x,b0,fmaf(av.y,b1,fmaf(av.z,b2,fmaf(av.w,b3,acc[i]))));
    }
  }
  float tv = tableZ ? tableZ[z*K + d] : 0.f;
  for (int i = 0; i < rows; i++){
    int n = rowsIdx[i];
    float v = alpha*acc[i] + tv;
    if (accum) v += C[n*K + d];
    C[n*K + d] = v;
  }
}

/* ------------------------- per-z tables + u ------------------------------ */
__global__ void tab_kernel(const float* __restrict__ We, const float* __restrict__ Wu1,
                           const float* __restrict__ Wsk1, const float* __restrict__ Wu2s,
                           const float* __restrict__ Wsk2, const float* __restrict__ Wms1,
                           const float* __restrict__ wr1){
  __shared__ float sh[K];
  __shared__ float red[4];
  int z = blockIdx.x, d = threadIdx.x;
  if (z == NE_){  /* u = Wms1 @ wr1 */
    float a = 0.f;
    for (int m = 0; m < K; m++) a = fmaf(Wms1[d*K + m], wr1[m], a);
    g_u[d] = a;
    return;
  }
  float a = 0.f, bb = 0.f;
  for (int c = 0; c < K; c++){
    float s = We[z*K + c];
    a  = fmaf(s, Wu1[c*K + d], a);
    bb = fmaf(s, Wsk1[(z*K + c)*K + d], bb);
  }
  g_sU1[z*K + d] = a;
  sh[d] = bb;
  __syncthreads();
  float t2 = 0.f, t3 = 0.f;
  for (int c = 0; c < K; c++){
    float s = sh[c];
    t2 = fmaf(s, Wu2s[c*K + d], t2);
    t3 = fmaf(s, Wsk2[(z*K + c)*K + d], t3);
  }
  g_tabU2[z*K + d] = t2;
  g_tabS2[z*K + d] = t3;
  /* t1[z] = sum_d ssk1[d]*wr1[d] */
  float p = sh[d]*wr1[d];
  #pragma unroll
  for (int o = 16; o; o >>= 1) p += __shfl_down_sync(0xffffffffu, p, o);
  if ((d & 31) == 0) red[d >> 5] = p;
  __syncthreads();
  if (d == 0) g_t1[z] = red[0] + red[1] + red[2] + red[3];
}

/* ------------------------------ transpose -------------------------------- */
__global__ void transpose_kernel(const float* __restrict__ src, float* __restrict__ dst, int nmat){
  int total = nmat*KK;
  for (int i = blockIdx.x*blockDim.x + threadIdx.x; i < total; i += gridDim.x*blockDim.x){
    int m = i/KK; int rem = i - m*KK; int r = rem/K; int c = rem - r*K;
    dst[m*KK + c*K + r] = src[i];
  }
}

/* ------------------------- node grouping by z + e0 ----------------------- */
__global__ void zcount_kernel(const int* __restrict__ nz, const int* __restrict__ batch,
                              const float* __restrict__ ae){
  int n = blockIdx.x*blockDim.x + threadIdx.x;
  if (n < NN){
    atomicAdd(&g_zcnt[nz[n]], 1);
    atomicAdd(&g_e0[batch[n]], ae[nz[n]]);
  }
}
__global__ void zscan_kernel(){
  if (threadIdx.x == 0 && blockIdx.x == 0){
    int acc = 0;
    for (int z = 0; z < NE_; z++){ g_zoff[z] = acc; acc += g_zcnt[z]; }
    g_zoff[NE_] = acc;
  }
}
__global__ void zscatter_kernel(const int* __restrict__ nz){
  int n = blockIdx.x*blockDim.x + threadIdx.x;
  if (n < NN){
    int z = nz[n];
    int p = atomicAdd(&g_zfill[z], 1);
    g_zperm[g_zoff[z] + p] = n;
  }
}

/* ------------------------- geometry + edge compaction -------------------- */
__global__ void geom_kernel(const float* __restrict__ pos, const float* __restrict__ shifts,
                            const int* __restrict__ ei, const int* __restrict__ nz){
  int e = blockIdx.x*blockDim.x + threadIdx.x;
  if (e >= EE) return;
  int s = ei[e], rc = ei[EE + e];
  float vx = pos[rc*3+0] - pos[s*3+0] + shifts[e*3+0];
  float vy = pos[rc*3+1] - pos[s*3+1] + shifts[e*3+1];
  float vz = pos[rc*3+2] - pos[s*3+2] + shifts[e*3+2];
  float rr = sqrtf(vx*vx + vy*vy + vz*vz + 1e-12f);
  if (rr < 5.0f){
    int i = atomicAdd(&g_nact, 1);
    g_esnd[i]=s; g_ercv[i]=rc; g_ezsnd[i]=nz[s];
    g_r[i]=rr;
    float inv = SQ3F / rr;
    g_Y1[i*3+0]=vx*inv; g_Y1[i*3+1]=vy*inv; g_Y1[i*3+2]=vz*inv;
    float x = rr*0.2f;
    float x2=x*x, x4=x2*x2, x5=x4*x;
    float fc = 1.f + x5*(-21.f + x*(35.f - 15.f*x));
    float invr = 1.f/rr;
    float cf = CB_F*invr*fc;
    float s1_, c1_;
    sincosf(PI_F*0.2f*rr, &s1_, &c1_);
    float sb = s1_, cb = c1_;
    #pragma unroll
    for (int b = 0; b < NB_; b++){
      g_ef[i*NB_ + b] = cf*sb;
      float ns = sb*c1_ + cb*s1_;
      float nc = cb*c1_ - sb*s1_;
      sb = ns; cb = nc;
    }
  }
}

/* --------------------------- layer-1 messages ---------------------------- */
__global__ void __launch_bounds__(128) msg1_kernel(const float* __restrict__ R1){
  int c = threadIdx.x;
  float r1a[NB_], r1b[NB_];
  #pragma unroll
  for (int b = 0; b < NB_; b++){ r1a[b]=R1[b*256 + c]; r1b[b]=R1[b*256 + 128 + c]; }
  int nact = g_nact;
  for (int e = blockIdx.x; e < nact; e += gridDim.x){
    int rcv = g_ercv[e], zs = g_ezsnd[e];
    float y0=g_Y1[e*3+0], y1=g_Y1[e*3+1], y2=g_Y1[e*3+2];
    float w0=0.f, w1=0.f;
    #pragma unroll
    for (int b = 0; b < NB_; b++){ float efb=g_ef[e*NB_+b]; w0=fmaf(efb,r1a[b],w0); w1=fmaf(efb,r1b[b],w1); }
    float sj = g_sU1[zs*K + c];
    atomicAdd(&g_A0[rcv*K + c], w0*sj);
    float t = w1*sj;
    atomicAdd(&g_A1[rcv*K + c],        t*y0);
    atomicAdd(&g_A1[NK + rcv*K + c],   t*y1);
    atomicAdd(&g_A1[2*NK + rcv*K + c], t*y2);
  }
}

/* ------------------------------ e1 --------------------------------------- */
__global__ void e1_kernel(const int* __restrict__ batch, const int* __restrict__ nz){
  int gt = blockIdx.x*blockDim.x + threadIdx.x;
  int n = gt >> 5, lane = gt & 31;
  if (n >= NN) return;
  float acc = 0.f;
  #pragma unroll
  for (int c = lane; c < K; c += 32) acc = fmaf(g_A0[n*K + c], g_u[c], acc);
  #pragma unroll
  for (int o = 16; o; o >>= 1) acc += __shfl_down_sync(0xffffffffu, acc, o);
  if (lane == 0) atomicAdd(&g_e1[batch[n]], ALPHA_*acc + g_t1[nz[n]]);
}

/* --------------------------- layer-2 messages ---------------------------- */
__global__ void __launch_bounds__(128) msg2_kernel(const float* __restrict__ R2){
  int c = threadIdx.x;
  float r2a[NB_], r2b[NB_];
  #pragma unroll
  for (int b = 0; b < NB_; b++){ r2a[b]=R2[b*512 + c]; r2b[b]=R2[b*512 + 128 + c]; }
  int nact = g_nact;
  for (int e = blockIdx.x; e < nact; e += gridDim.x){
    int snd = g_esnd[e], rcv = g_ercv[e];
    float y0=g_Y1[e*3+0], y1=g_Y1[e*3+1], y2=g_Y1[e*3+2];
    float w00=0.f, w110=0.f;
    #pragma unroll
    for (int b = 0; b < NB_; b++){ float efb=g_ef[e*NB_+b]; w00=fmaf(efb,r2a[b],w00); w110=fmaf(efb,r2b[b],w110); }
    float sj = g_sU2[snd*K + c];
    float vj0=g_vU2[snd*K+c], vj1=g_vU2[NK+snd*K+c], vj2=g_vU2[2*NK+snd*K+c];
    float dot = vj0*y0 + vj1*y1 + vj2*y2;
    float m = fmaf(w00, sj, w110*dot*INV_SQ3);
    atomicAdd(&g_A2[rcv*K + c], m);
  }
}

/* ----------------------- MLP head: e2 + ds2 ------------------------------ */
__global__ void __launch_bounds__(128) mlp_kernel(const float* __restrict__ Wmlp,
    const float* __restrict__ wout, const int* __restrict__ batch){
  __shared__ float srow[K];
  __shared__ float gj[16];
  __shared__ float hpart[16];
  int tid = threadIdx.x;
  for (int n = blockIdx.x; n < NN; n += gridDim.x){
    srow[tid] = g_s2[n*K + tid];
    __syncthreads();
    if (tid < 16){
      float uu = 0.f;
      for (int c = 0; c < K; c++) uu = fmaf(srow[c], Wmlp[c*16 + tid], uu);
      float sig = 1.f/(1.f + __expf(-uu));
      hpart[tid] = uu*sig*wout[tid];
      gj[tid] = wout[tid]*sig*(1.f + uu*(1.f - sig));
    }
    __syncthreads();
    if (tid == 0){
      float s = 0.f;
      #pragma unroll
      for (int j = 0; j < 16; j++) s += hpart[j];
      atomicAdd(&g_e2[batch[n]], s);
    }
    float ds = 0.f;
    #pragma unroll
    for (int j = 0; j < 16; j++) ds = fmaf(Wmlp[tid*16 + j], gj[j], ds);
    g_ds2[n*K + tid] = ds;
    __syncthreads();
  }
}

/* ------------------------- backward: layer-2 edges ----------------------- */
__device__ __forceinline__ float warpsum(float v){
  #pragma unroll
  for (int o = 16; o; o >>= 1) v += __shfl_down_sync(0xffffffffu, v, o);
  return v;
}

__global__ void __launch_bounds__(128) bwd2_kernel(const float* __restrict__ R2){
  __shared__ float red[4][11];
  int c = threadIdx.x;
  int warp = c >> 5, lane = c & 31;
  float r2a[NB_], r2b[NB_];
  #pragma unroll
  for (int b = 0; b < NB_; b++){ r2a[b]=R2[b*512 + c]; r2b[b]=R2[b*512 + 128 + c]; }
  int nact = g_nact;
  for (int e = blockIdx.x; e < nact; e += gridDim.x){
    int snd = g_esnd[e], rcv = g_ercv[e];
    float y0=g_Y1[e*3+0], y1=g_Y1[e*3+1], y2=g_Y1[e*3+2];
    float w00=0.f, w110=0.f;
    #pragma unroll
    for (int b = 0; b < NB_; b++){ float efb=g_ef[e*NB_+b]; w00=fmaf(efb,r2a[b],w00); w110=fmaf(efb,r2b[b],w110); }
    float dm = g_dA2[rcv*K + c];
    float sj = g_sU2[snd*K + c];
    float vj0=g_vU2[snd*K+c], vj1=g_vU2[NK+snd*K+c], vj2=g_vU2[2*NK+snd*K+c];
    float dot = vj0*y0 + vj1*y1 + vj2*y2;
    atomicAdd(&g_Dsj2[snd*K + c], dm*w00);
    float ddot = dm*w110*INV_SQ3;
    atomicAdd(&g_Dvj[snd*K + c],        ddot*y0);
    atomicAdd(&g_Dvj[NK + snd*K + c],   ddot*y1);
    atomicAdd(&g_Dvj[2*NK + snd*K + c], ddot*y2);
    float p[11];
    float dw00 = dm*sj, dw110 = dm*dot*INV_SQ3;
    #pragma unroll
    for (int b = 0; b < NB_; b++) p[b] = fmaf(dw00, r2a[b], dw110*r2b[b]);
    p[8] = ddot*vj0; p[9] = ddot*vj1; p[10] = ddot*vj2;
    #pragma unroll
    for (int k = 0; k < 11; k++){
      float v = warpsum(p[k]);
      if (lane == 0) red[warp][k] = v;
    }
    __syncthreads();
    if (c < 11){
      float v = red[0][c] + red[1][c] + red[2][c] + red[3][c];
      if (c < 8) g_def[e*NB_ + c] = v;
      else       g_dY1b[e*3 + (c-8)] = v;
    }
    __syncthreads();
  }
}

/* ------------------------- backward: layer-1 edges ----------------------- */
__global__ void __launch_bounds__(128) bwd1_kernel(const float* __restrict__ R1){
  __shared__ float red[4][11];
  int c = threadIdx.x;
  int warp = c >> 5, lane = c & 31;
  float r1a[NB_], r1b[NB_];
  #pragma unroll
  for (int b = 0; b < NB_; b++){ r1a[b]=R1[b*256 + c]; r1b[b]=R1[b*256 + 128 + c]; }
  int nact = g_nact;
  for (int e = blockIdx.x; e < nact; e += gridDim.x){
    int rcv = g_ercv[e], zs = g_ezsnd[e];
    float y0=g_Y1[e*3+0], y1=g_Y1[e*3+1], y2=g_Y1[e*3+2];
    float w1 = 0.f;
    #pragma unroll
    for (int b = 0; b < NB_; b++){ float efb=g_ef[e*NB_+b]; w1 = fmaf(efb, r1b[b], w1); }
    float dm0 = g_dA0[rcv*K + c];
    float dm10 = g_dA1[rcv*K + c];
    float dm11 = g_dA1[NK + rcv*K + c];
    float dm12 = g_dA1[2*NK + rcv*K + c];
    float sj = g_sU1[zs*K + c];
    float dw0 = dm0*sj;
    float t = dm10*y0 + dm11*y1 + dm12*y2;
    float dw1 = t*sj;
    float p[11];
    #pragma unroll
    for (int b = 0; b < NB_; b++) p[b] = fmaf(dw0, r1a[b], dw1*r1b[b]);
    float ws = w1*sj;
    p[8] = dm10*ws; p[9] = dm11*ws; p[10] = dm12*ws;
    #pragma unroll
    for (int k = 0; k < 11; k++){
      float v = warpsum(p[k]);
      if (lane == 0) red[warp][k] = v;
    }
    __syncthreads();
    if (c < 11){
      float v = red[0][c] + red[1][c] + red[2][c] + red[3][c];
      if (c < 8) g_def[e*NB_ + c] += v;
      else       g_dY1b[e*3 + (c-8)] += v;
    }
    __syncthreads();
  }
}

/* ------------------------- geometry backward ----------------------------- */
__global__ void geom_bwd_kernel(float* __restrict__ F){
  int nact = g_nact;
  for (int e = blockIdx.x*blockDim.x + threadIdx.x; e < nact; e += gridDim.x*blockDim.x){
    float rr = g_r[e];
    float y0=g_Y1[e*3+0], y1=g_Y1[e*3+1], y2=g_Y1[e*3+2];
    float v0 = y0*rr*INV_SQ3, v1 = y1*rr*INV_SQ3, v2 = y2*rr*INV_SQ3;
    float x = rr*0.2f;
    float x2=x*x, x4=x2*x2, x5=x4*x;
    float fc = 1.f + x5*(-21.f + x*(35.f - 15.f*x));
    float omx = 1.f - x;
    float dfcdr = -21.f*x4*omx*omx;
    float invr = 1.f/rr;
    float s1_, c1_;
    sincosf(PI_F*0.2f*rr, &s1_, &c1_);
    float sb = s1_, cb = c1_;
    float dr = 0.f;
    #pragma unroll
    for (int b = 0; b < NB_; b++){
      float a = (float)(b+1)*(PI_F*0.2f);
      float debdr = CB_F*((a*cb*rr - sb)*invr*invr*fc + sb*invr*dfcdr);
      dr = fmaf(g_def[e*NB_ + b], debdr, dr);
      float ns = sb*c1_ + cb*s1_;
      float nc = cb*c1_ - sb*s1_;
      sb = ns; cb = nc;
    }
    float dY0=g_dY1b[e*3+0], dY1v=g_dY1b[e*3+1], dY2=g_dY1b[e*3+2];
    float vd = v0*dY0 + v1*dY1v + v2*dY2;
    float c1c = SQ3F*invr;
    float c2c = SQ3F*vd*invr*invr*invr;
    float dv0 = dr*v0*invr + c1c*dY0 - c2c*v0;
    float dv1 = dr*v1*invr + c1c*dY1v - c2c*v1;
    float dv2 = dr*v2*invr + c1c*dY2 - c2c*v2;
    int snd = g_esnd[e], rcv = g_ercv[e];
    atomicAdd(&F[snd*3+0],  dv0); atomicAdd(&F[snd*3+1],  dv1); atomicAdd(&F[snd*3+2],  dv2);
    atomicAdd(&F[rcv*3+0], -dv0); atomicAdd(&F[rcv*3+1], -dv1); atomicAdd(&F[rcv*3+2], -dv2);
  }
}

/* ------------------------------- finalize -------------------------------- */
__global__ void finalize_kernel(float* __restrict__ out){
  int g = threadIdx.x;
  if (g < GG){
    float a = g_e0[g], b = g_e1[g], c = g_e2[g];
    out[g] = a + b + c;
    out[GG + g*3 + 0] = a;
    out[GG + g*3 + 1] = b;
    out[GG + g*3 + 2] = c;
  }
}

/* ------------------------------ host helpers ----------------------------- */
static void gops_init(GOps& P){ P.count = 0; }
static void gops_add(GOps& P, const float* A, const float* B, float* C, int M,
                     float alpha, int accum, const float* table, const int* nz,
                     const float* bias){
  int i = P.count++;
  P.A[i]=A; P.B[i]=B; P.C[i]=C; P.M[i]=M; P.alpha[i]=alpha; P.accum[i]=accum;
  P.table[i]=table; P.nz[i]=nz; P.bias[i]=bias;
  P.tiles[i] = CDIV(M,64);
}
static int gops_total(const GOps& P){
  int t = 0; for (int i = 0; i < P.count; i++) t += P.tiles[i];
  return t;
}

/* ------------------------------ launch ----------------------------------- */
extern "C" void kernel_launch(void* const* d_in, const int* in_sizes, int n_in,
                              void* d_out, int out_size){
  const float *positions, *shifts, *ae, *We, *R1, *Wu1, *Wms1, *Wmv1, *Wsk1, *wr1;
  const float *R2, *Wu2s, *Wu2v, *Wms2, *Wsk2, *Wmlp, *wout;
  const int *edge_index, *node_z, *batch;

  if (in_sizes[2] == 2*EE){  /* setup_inputs dict order */
    positions=(const float*)d_in[0]; shifts=(const float*)d_in[1];
    edge_index=(const int*)d_in[2]; node_z=(const int*)d_in[3]; batch=(const int*)d_in[4];
    ae=(const float*)d_in[5]; We=(const float*)d_in[6]; R1=(const float*)d_in[7];
    Wu1=(const float*)d_in[8]; Wms1=(const float*)d_in[9]; Wmv1=(const float*)d_in[10];
    Wsk1=(const float*)d_in[11]; wr1=(const float*)d_in[12]; R2=(const float*)d_in[13];
    Wu2s=(const float*)d_in[14]; Wu2v=(const float*)d_in[15]; Wms2=(const float*)d_in[16];
    Wsk2=(const float*)d_in[17]; Wmlp=(const float*)d_in[18]; wout=(const float*)d_in[19];
  } else {                   /* reference signature order */
    positions=(const float*)d_in[0]; shifts=(const float*)d_in[1];
    ae=(const float*)d_in[2]; We=(const float*)d_in[3]; R1=(const float*)d_in[4];
    Wu1=(const float*)d_in[5]; Wms1=(const float*)d_in[6]; Wmv1=(const float*)d_in[7];
    Wsk1=(const float*)d_in[8]; wr1=(const float*)d_in[9]; R2=(const float*)d_in[10];
    Wu2s=(const float*)d_in[11]; Wu2v=(const float*)d_in[12]; Wms2=(const float*)d_in[13];
    Wsk2=(const float*)d_in[14]; Wmlp=(const float*)d_in[15]; wout=(const float*)d_in[16];
    edge_index=(const int*)d_in[17]; node_z=(const int*)d_in[18]; batch=(const int*)d_in[19];
  }
  float* out = (float*)d_out;

  float *p_A0,*p_A1,*p_sU2,*p_vU2,*p_A2,*p_s2,*p_ds2,*p_dA2,*p_Dsj2,*p_Dvj,*p_dA0,*p_dA1;
  float *p_WF,*p_WFT,*p_WtE,*p_tabU2,*p_tabS2,*p_u;
  cudaGetSymbolAddress((void**)&p_A0, g_A0);     cudaGetSymbolAddress((void**)&p_A1, g_A1);
  cudaGetSymbolAddress((void**)&p_sU2, g_sU2);   cudaGetSymbolAddress((void**)&p_vU2, g_vU2);
  cudaGetSymbolAddress((void**)&p_A2, g_A2);     cudaGetSymbolAddress((void**)&p_s2, g_s2);
  cudaGetSymbolAddress((void**)&p_ds2, g_ds2);   cudaGetSymbolAddress((void**)&p_dA2, g_dA2);
  cudaGetSymbolAddress((void**)&p_Dsj2, g_Dsj2); cudaGetSymbolAddress((void**)&p_Dvj, g_Dvj);
  cudaGetSymbolAddress((void**)&p_dA0, g_dA0);   cudaGetSymbolAddress((void**)&p_dA1, g_dA1);
  cudaGetSymbolAddress((void**)&p_WF, g_WF);     cudaGetSymbolAddress((void**)&p_WFT, g_WFT);
  cudaGetSymbolAddress((void**)&p_WtE, g_WtE);   cudaGetSymbolAddress((void**)&p_tabU2, g_tabU2);
  cudaGetSymbolAddress((void**)&p_tabS2, g_tabS2); cudaGetSymbolAddress((void**)&p_u, g_u);

  zero_kernel<<<4096, 512>>>(out, out_size);

  /* fused weight precompute: WF1, Wfuse, WF2z (12 x 128x128 GEMMs, 1 launch) */
  {
    GOps P; gops_init(P);
    gops_add(P, Wms1, Wu2s, p_WF,        K, 1.f, 0, 0, 0, 0);
    gops_add(P, Wmv1, Wu2v, p_WF + KK,   K, 1.f, 0, 0, 0, 0);
    for (int z = 0; z < NE_; z++)
      gops_add(P, Wms1, Wsk2 + z*KK, p_WF + (2+z)*KK, K, 1.f, 0, 0, 0, 0);
    mgemm_kernel<<<gops_total(P), 256>>>(P);
  }
  transpose_kernel<<<96, 512>>>(p_WF, p_WFT, 12);
  transpose_kernel<<<32, 512>>>(Wms2, p_WtE, 1);
  tab_kernel<<<NE_ + 1, K>>>(We, Wu1, Wsk1, Wu2s, Wsk2, Wms1, wr1);

  zcount_kernel<<<CDIV(NN,256), 256>>>(node_z, batch, ae);
  zscan_kernel<<<1, 1>>>();
  zscatter_kernel<<<CDIV(NN,256), 256>>>(node_z);
  geom_kernel<<<CDIV(EE,256), 256>>>(positions, shifts, edge_index, node_z);

  /* ------ layer 1 forward ------ */
  msg1_kernel<<<2048, 128>>>(R1);

  /* stage C: sU2 = a*A0@WF1 + tabU2[z] ; vU2 = a*A1@Wfuse (one launch) */
  {
    GOps P; gops_init(P);
    gops_add(P, p_A0, p_WF,      p_sU2, NN,   ALPHA_, 0, p_tabU2, node_z, 0);
    gops_add(P, p_A1, p_WF + KK, p_vU2, 3*NN, ALPHA_, 0, 0, 0, 0);
    mgemm_kernel<<<gops_total(P), 256>>>(P);
  }
  e1_kernel<<<CDIV(NN*32,256), 256>>>(batch, node_z);
  /* s2 partial = a*A0@WF2z + tabS2[z] (grouped; independent of msg2) */
  {
    dim3 grid(CDIV(NN,32), NE_);
    gemm_grouped_kernel<<<grid, 128>>>(p_A0, p_WF + 2*KK, p_s2, ALPHA_, 0, p_tabS2);
  }

  /* ------ layer 2 forward ------ */
  msg2_kernel<<<2048, 128>>>(R2);
  {
    GOps P; gops_init(P);
    gops_add(P, p_A2, Wms2, p_s2, NN, ALPHA_, 1, 0, 0, 0);
    mgemm_kernel<<<gops_total(P), 256>>>(P);
  }
  mlp_kernel<<<2048, 128>>>(Wmlp, wout, batch);

  /* ------ backward ------ */
  {
    GOps P; gops_init(P);
    gops_add(P, p_ds2, p_WtE, p_dA2, NN, ALPHA_, 0, 0, 0, 0);
    mgemm_kernel<<<gops_total(P), 256>>>(P);
  }
  /* dA0 partial = a*ds2@WF2z^T (grouped; only needs ds2) */
  {
    dim3 grid(CDIV(NN,32), NE_);
    gemm_grouped_kernel<<<grid, 128>>>(p_ds2, p_WFT + 2*KK, p_dA0, ALPHA_, 0, 0);
  }
  bwd2_kernel<<<2048, 128>>>(R2);
  /* stage I: dA0 += a*(Dsj2@WF1^T + u^T) ; dA1 = a*Dvj@Wfuse^T (one launch) */
  {
    GOps P; gops_init(P);
    gops_add(P, p_Dsj2, p_WFT,      p_dA0, NN,   ALPHA_, 1, 0, 0, p_u);
    gops_add(P, p_Dvj,  p_WFT + KK, p_dA1, 3*NN, ALPHA_, 0, 0, 0, 0);
    mgemm_kernel<<<gops_total(P), 256>>>(P);
  }
  bwd1_kernel<<<2048, 128>>>(R1);
  geom_bwd_kernel<<<1024, 256>>>(out + GG + 3*GG);
  finalize_kernel<<<1, 32>>>(out);
}